// round 16
// baseline (speedup 1.0000x reference)
#include <cuda_runtime.h>
#include <cuda_fp16.h>
#include <cstdint>

#define N_NODES 50000
#define N_EDGES 600000
#define HID     128
#define N_GRAPHS 512
#define BN_EPS  1e-5f
#define SCAN_BLOCKS ((N_NODES + 255) / 256)   // 196

// ---------------- scratch ----------------
__device__ float g_h0[N_NODES * HID];
__device__ float g_h1[N_NODES * HID];
__device__ float g_neigh[N_NODES * HID];
__device__ float g_t2[N_NODES * HID];
__device__ __half g_hf[N_NODES * HID];   // fp16 mirror of layer outputs (gather source)

__device__ int   g_deg[N_NODES];
__device__ int   g_off[N_NODES + 1];
__device__ int   g_cur[N_NODES];
__device__ int   g_csr[N_EDGES];
__device__ float g_invdeg[N_NODES];
__device__ int   g_blk[SCAN_BLOCKS];

__device__ float g_bnsum[3 * HID];
__device__ float g_bnsq[3 * HID];

// ---------------- helpers ----------------
__device__ __forceinline__ unsigned long long pack_dup(float x) {
    unsigned long long d;
    asm("mov.b64 %0,{%1,%1};" : "=l"(d) : "f"(x));
    return d;
}

// 128-row transposed A layout (GIN): (k,row) at k*132 + 4*(k>>2) + row
#define AS_IDX(k, row) ((k) * 132 + 4 * ((k) >> 2) + (row))
#define AS_SIZE 4256
// 64-row transposed A layout (SAGE)
#define AS64_IDX(k, row) ((k) * 68 + 4 * ((k) >> 2) + (row))
#define AS64_SIZE 2208
// B layout: (k,n) at k*132 + n
#define BS_IDX(k, n) ((k) * 132 + (n))
#define BS_SIZE 4224
#define TS_SIZE 17024

// ---------------- setup kernels ----------------
__global__ void zero_init_kernel() {
    int i = blockIdx.x * blockDim.x + threadIdx.x;
    if (i < N_NODES) g_deg[i] = 0;
    if (i < 3 * HID) { g_bnsum[i] = 0.f; g_bnsq[i] = 0.f; }
}

// 4 edges per thread (int4 loads) -> MLP 4
__global__ void hist_kernel(const int* __restrict__ dst) {
    int t = blockIdx.x * blockDim.x + threadIdx.x;
    int base = t * 4;
    if (base + 4 <= N_EDGES) {
        int4 d = __ldg((const int4*)&dst[base]);
        atomicAdd(&g_deg[d.x], 1);
        atomicAdd(&g_deg[d.y], 1);
        atomicAdd(&g_deg[d.z], 1);
        atomicAdd(&g_deg[d.w], 1);
    } else {
        for (int e = base; e < N_EDGES; e++) atomicAdd(&g_deg[__ldg(&dst[e])], 1);
    }
}

__global__ void scan_part1_kernel() {
    __shared__ int sh[256];
    int t = threadIdx.x;
    int i = blockIdx.x * 256 + t;
    sh[t] = (i < N_NODES) ? g_deg[i] : 0;
    __syncthreads();
    for (int off = 128; off > 0; off >>= 1) {
        if (t < off) sh[t] += sh[t + off];
        __syncthreads();
    }
    if (t == 0) g_blk[blockIdx.x] = sh[0];
}

// fused: every block scans block sums in smem, then its local scan
__global__ void scan_part2_kernel() {
    __shared__ int bs[256];
    __shared__ int sh[256];
    int t = threadIdx.x;
    bs[t] = (t < SCAN_BLOCKS) ? g_blk[t] : 0;
    __syncthreads();
    for (int off = 1; off < 256; off <<= 1) {
        int u = (t >= off) ? bs[t - off] : 0;
        __syncthreads();
        bs[t] += u;
        __syncthreads();
    }
    if (blockIdx.x == 0 && t == 0) g_off[N_NODES] = bs[SCAN_BLOCKS - 1];
    int base = bs[blockIdx.x] - ((blockIdx.x < SCAN_BLOCKS) ? g_blk[blockIdx.x] : 0);

    int i = blockIdx.x * 256 + t;
    int d = (i < N_NODES) ? g_deg[i] : 0;
    sh[t] = d;
    __syncthreads();
    for (int off = 1; off < 256; off <<= 1) {
        int u = (t >= off) ? sh[t - off] : 0;
        __syncthreads();
        sh[t] += u;
        __syncthreads();
    }
    if (i < N_NODES) {
        int run = base + sh[t] - d;
        g_off[i] = run;
        g_cur[i] = run;
        g_invdeg[i] = 1.0f / (float)max(d, 1);
    }
}

// 4 edges per thread (int4 loads of src and dst)
__global__ void scatter_kernel(const int* __restrict__ src, const int* __restrict__ dst) {
    int t = blockIdx.x * blockDim.x + threadIdx.x;
    int base = t * 4;
    if (base + 4 <= N_EDGES) {
        int4 d = __ldg((const int4*)&dst[base]);
        int4 s = __ldg((const int4*)&src[base]);
        int p0 = atomicAdd(&g_cur[d.x], 1);
        int p1 = atomicAdd(&g_cur[d.y], 1);
        int p2 = atomicAdd(&g_cur[d.z], 1);
        int p3 = atomicAdd(&g_cur[d.w], 1);
        g_csr[p0] = s.x;
        g_csr[p1] = s.y;
        g_csr[p2] = s.z;
        g_csr[p3] = s.w;
    } else {
        for (int e = base; e < N_EDGES; e++) {
            int p = atomicAdd(&g_cur[__ldg(&dst[e])], 1);
            g_csr[p] = __ldg(&src[e]);
        }
    }
}

// ---------------- GIN aggregation (warp per node, fp32 gather) ----------------
__global__ void gin_agg_kernel(const float* __restrict__ x) {
    int w = (blockIdx.x * blockDim.x + threadIdx.x) >> 5;
    int lane = threadIdx.x & 31;
    if (w >= N_NODES) return;
    const float4* x4 = (const float4*)x;
    float4 acc = __ldg(&x4[w * 32 + lane]);
    int e = g_off[w], end = g_off[w + 1];
    for (; e + 4 <= end; e += 4) {
        int s0 = g_csr[e + 0], s1 = g_csr[e + 1], s2 = g_csr[e + 2], s3 = g_csr[e + 3];
        float4 v0 = __ldg(&x4[s0 * 32 + lane]);
        float4 v1 = __ldg(&x4[s1 * 32 + lane]);
        float4 v2 = __ldg(&x4[s2 * 32 + lane]);
        float4 v3 = __ldg(&x4[s3 * 32 + lane]);
        acc.x += v0.x + v1.x + v2.x + v3.x;
        acc.y += v0.y + v1.y + v2.y + v3.y;
        acc.z += v0.z + v1.z + v2.z + v3.z;
        acc.w += v0.w + v1.w + v2.w + v3.w;
    }
    for (; e < end; e++) {
        int s0 = g_csr[e];
        float4 v0 = __ldg(&x4[s0 * 32 + lane]);
        acc.x += v0.x; acc.y += v0.y; acc.z += v0.z; acc.w += v0.w;
    }
    ((float4*)g_h0)[w * 32 + lane] = acc;
}

__device__ __forceinline__ float4 bn_relu4(float4 h, float4 sc, float4 sh) {
    float4 r;
    r.x = fmaxf(fmaf(h.x, sc.x, sh.x), 0.f);
    r.y = fmaxf(fmaf(h.y, sc.y, sh.y), 0.f);
    r.z = fmaxf(fmaf(h.z, sc.z, sh.z), 0.f);
    r.w = fmaxf(fmaf(h.w, sc.w, sh.w), 0.f);
    return r;
}

__device__ __forceinline__ void bn_coeffs(int layer, int c0,
                                          const float* __restrict__ gamma,
                                          const float* __restrict__ beta,
                                          float4& sc, float4& sh) {
    const float invn = 1.0f / (float)N_NODES;
    float4 s1 = *(const float4*)&g_bnsum[layer * HID + c0];
    float4 s2 = *(const float4*)&g_bnsq[layer * HID + c0];
    float4 gm = __ldg((const float4*)&gamma[c0]);
    float4 bt = __ldg((const float4*)&beta[c0]);
    float m, var;
    m = s1.x * invn; var = fmaxf(s2.x * invn - m * m, 0.f);
    sc.x = gm.x * rsqrtf(var + BN_EPS); sh.x = bt.x - m * sc.x;
    m = s1.y * invn; var = fmaxf(s2.y * invn - m * m, 0.f);
    sc.y = gm.y * rsqrtf(var + BN_EPS); sh.y = bt.y - m * sc.y;
    m = s1.z * invn; var = fmaxf(s2.z * invn - m * m, 0.f);
    sc.z = gm.z * rsqrtf(var + BN_EPS); sh.z = bt.z - m * sc.z;
    m = s1.w * invn; var = fmaxf(s2.w * invn - m * m, 0.f);
    sc.w = gm.w * rsqrtf(var + BN_EPS); sh.w = bt.w - m * sc.w;
}

// SAGE aggregation: neighbors from fp16 mirror only (fp32 neigh out)
__global__ void sage_agg_kernel(float* __restrict__ neigh,
                                const float* __restrict__ gamma,
                                const float* __restrict__ beta,
                                int layer) {
    int w = (blockIdx.x * blockDim.x + threadIdx.x) >> 5;
    int lane = threadIdx.x & 31;
    if (w >= N_NODES) return;
    float4 sc, sh;
    bn_coeffs(layer, lane * 4, gamma, beta, sc, sh);

    const uint2* hh = (const uint2*)g_hf;
    float4 acc = make_float4(0.f, 0.f, 0.f, 0.f);
    int e = g_off[w], end = g_off[w + 1];
#define GATH_H(sx, vr) { \
        uint2 u = __ldg(&hh[(sx) * 32 + lane]); \
        float2 f0 = __half22float2(*(__half2*)&u.x); \
        float2 f1 = __half22float2(*(__half2*)&u.y); \
        vr = bn_relu4(make_float4(f0.x, f0.y, f1.x, f1.y), sc, sh); }
    for (; e + 4 <= end; e += 4) {
        int s0 = g_csr[e + 0], s1 = g_csr[e + 1], s2 = g_csr[e + 2], s3 = g_csr[e + 3];
        float4 v0, v1, v2, v3;
        GATH_H(s0, v0); GATH_H(s1, v1); GATH_H(s2, v2); GATH_H(s3, v3);
        acc.x += v0.x + v1.x + v2.x + v3.x;
        acc.y += v0.y + v1.y + v2.y + v3.y;
        acc.z += v0.z + v1.z + v2.z + v3.z;
        acc.w += v0.w + v1.w + v2.w + v3.w;
    }
    for (; e < end; e++) {
        int s0 = g_csr[e];
        float4 v0;
        GATH_H(s0, v0);
        acc.x += v0.x; acc.y += v0.y; acc.z += v0.z; acc.w += v0.w;
    }
#undef GATH_H
    float id = g_invdeg[w];
    acc.x *= id; acc.y *= id; acc.z *= id; acc.w *= id;
    ((float4*)neigh)[w * 32 + lane] = acc;
}

// ---------------- GEMM building blocks ----------------
__device__ __forceinline__ void stage_A(float* Asf, const float* __restrict__ A,
                                        int rowBase, int kc, int M, int tid) {
#pragma unroll
    for (int i = 0; i < 4; i++) {
        int f = tid + 256 * i;
        int row = f >> 3, kq = f & 7;
        int grow = rowBase + row; if (grow >= M) grow = M - 1;
        float4 v = __ldg((const float4*)&A[grow * HID + kc + kq * 4]);
        int k0 = kq * 4;
        Asf[AS_IDX(k0 + 0, row)] = v.x;
        Asf[AS_IDX(k0 + 1, row)] = v.y;
        Asf[AS_IDX(k0 + 2, row)] = v.z;
        Asf[AS_IDX(k0 + 3, row)] = v.w;
    }
}

__device__ __forceinline__ void stage_A64(float* Asf, const float* __restrict__ A,
                                          int rowBase, int kc, int M, int tid) {
#pragma unroll
    for (int i = 0; i < 2; i++) {
        int f = tid + 256 * i;
        int row = f >> 3, kq = f & 7;
        int grow = rowBase + row; if (grow >= M) grow = M - 1;
        float4 v = __ldg((const float4*)&A[grow * HID + kc + kq * 4]);
        int k0 = kq * 4;
        Asf[AS64_IDX(k0 + 0, row)] = v.x;
        Asf[AS64_IDX(k0 + 1, row)] = v.y;
        Asf[AS64_IDX(k0 + 2, row)] = v.z;
        Asf[AS64_IDX(k0 + 3, row)] = v.w;
    }
}

// stage bn_relu(hprev) 64-row chunk: coeffs computed inline
__device__ __forceinline__ void stage_A64_bn(float* Asf, const float* __restrict__ A,
                                             int rowBase, int kc, int M, int tid,
                                             int layer,
                                             const float* __restrict__ gamma,
                                             const float* __restrict__ beta) {
#pragma unroll
    for (int i = 0; i < 2; i++) {
        int f = tid + 256 * i;
        int row = f >> 3, kq = f & 7;
        int grow = rowBase + row; if (grow >= M) grow = M - 1;
        int c0 = kc + kq * 4;
        float4 sc, sh;
        bn_coeffs(layer, c0, gamma, beta, sc, sh);
        float4 v = bn_relu4(__ldg((const float4*)&A[grow * HID + c0]), sc, sh);
        int k0 = kq * 4;
        Asf[AS64_IDX(k0 + 0, row)] = v.x;
        Asf[AS64_IDX(k0 + 1, row)] = v.y;
        Asf[AS64_IDX(k0 + 2, row)] = v.z;
        Asf[AS64_IDX(k0 + 3, row)] = v.w;
    }
}

__device__ __forceinline__ void stage_B(float* Bsf, const float* __restrict__ W,
                                        int kc, int tid) {
#pragma unroll
    for (int i = 0; i < 4; i++) {
        int f = tid + 256 * i;
        int k = f >> 5, n4 = f & 31;
        float4 v = __ldg((const float4*)&W[(kc + k) * HID + n4 * 4]);
        *(float4*)&Bsf[BS_IDX(k, n4 * 4)] = v;
    }
}

__device__ __forceinline__ void compute_chunk(const float* __restrict__ Afrag,
                                              const float* __restrict__ Bsf,
                                              int trow, int tcol,
                                              unsigned long long acc[8][4]) {
#pragma unroll 8
    for (int k = 0; k < 32; k++) {
        const float* ar = &Afrag[k * 132 + 4 * (k >> 2) + trow * 16];
        unsigned long long a[8];
        ulonglong2 t;
        t = *(const ulonglong2*)(ar + 0);  a[0] = t.x; a[1] = t.y;
        t = *(const ulonglong2*)(ar + 4);  a[2] = t.x; a[3] = t.y;
        t = *(const ulonglong2*)(ar + 8);  a[4] = t.x; a[5] = t.y;
        t = *(const ulonglong2*)(ar + 12); a[6] = t.x; a[7] = t.y;
        float4 b4 = *(const float4*)&Bsf[BS_IDX(k, tcol * 4)];
        unsigned long long bb0 = pack_dup(b4.x);
        unsigned long long bb1 = pack_dup(b4.y);
        unsigned long long bb2 = pack_dup(b4.z);
        unsigned long long bb3 = pack_dup(b4.w);
#pragma unroll
        for (int r = 0; r < 8; r++) {
            asm("fma.rn.f32x2 %0,%1,%2,%0;" : "+l"(acc[r][0]) : "l"(a[r]), "l"(bb0));
            asm("fma.rn.f32x2 %0,%1,%2,%0;" : "+l"(acc[r][1]) : "l"(a[r]), "l"(bb1));
            asm("fma.rn.f32x2 %0,%1,%2,%0;" : "+l"(acc[r][2]) : "l"(a[r]), "l"(bb2));
            asm("fma.rn.f32x2 %0,%1,%2,%0;" : "+l"(acc[r][3]) : "l"(a[r]), "l"(bb3));
        }
    }
}

__device__ __forceinline__ void compute_chunk64(const float* __restrict__ Afrag,
                                                const float* __restrict__ Bsf,
                                                int trow, int tcol,
                                                unsigned long long acc[4][4]) {
#pragma unroll 8
    for (int k = 0; k < 32; k++) {
        const float* ar = &Afrag[k * 68 + 4 * (k >> 2) + trow * 8];
        unsigned long long a[4];
        ulonglong2 t;
        t = *(const ulonglong2*)(ar + 0); a[0] = t.x; a[1] = t.y;
        t = *(const ulonglong2*)(ar + 4); a[2] = t.x; a[3] = t.y;
        float4 b4 = *(const float4*)&Bsf[BS_IDX(k, tcol * 4)];
        unsigned long long bb0 = pack_dup(b4.x);
        unsigned long long bb1 = pack_dup(b4.y);
        unsigned long long bb2 = pack_dup(b4.z);
        unsigned long long bb3 = pack_dup(b4.w);
#pragma unroll
        for (int r = 0; r < 4; r++) {
            asm("fma.rn.f32x2 %0,%1,%2,%0;" : "+l"(acc[r][0]) : "l"(a[r]), "l"(bb0));
            asm("fma.rn.f32x2 %0,%1,%2,%0;" : "+l"(acc[r][1]) : "l"(a[r]), "l"(bb1));
            asm("fma.rn.f32x2 %0,%1,%2,%0;" : "+l"(acc[r][2]) : "l"(a[r]), "l"(bb2));
            asm("fma.rn.f32x2 %0,%1,%2,%0;" : "+l"(acc[r][3]) : "l"(a[r]), "l"(bb3));
        }
    }
}

__device__ __forceinline__ void store_pair_h(__half* __restrict__ outh, int row, int c0,
                                             const float* v) {
    __half2 a = __float22half2_rn(make_float2(v[0], v[1]));
    __half2 b = __float22half2_rn(make_float2(v[2], v[3]));
    uint2 u;
    u.x = *(uint32_t*)&a; u.y = *(uint32_t*)&b;
    *(uint2*)&outh[row * HID + c0] = u;
}

// 128-row epilogue (GIN): bias + store f32 + f16 mirror + BN stats
__device__ __forceinline__ void gemm_epilogue(unsigned long long acc[8][4],
                                              const float* __restrict__ bias,
                                              float* __restrict__ out,
                                              __half* __restrict__ outh,
                                              float* csum, float* csq,
                                              float* statS, float* statQ,
                                              int rowBase, int trow, int tcol,
                                              int M, int tid) {
    float4 bias4 = __ldg((const float4*)&bias[tcol * 4]);
    float bv[4] = { bias4.x, bias4.y, bias4.z, bias4.w };
    float lsum[4] = {0, 0, 0, 0}, lsq[4] = {0, 0, 0, 0};
#pragma unroll
    for (int r = 0; r < 8; r++) {
        float vlo[4], vhi[4];
#pragma unroll
        for (int c = 0; c < 4; c++) {
            unsigned long long u = acc[r][c];
            vlo[c] = __uint_as_float((unsigned)u) + bv[c];
            vhi[c] = __uint_as_float((unsigned)(u >> 32)) + bv[c];
        }
        int row0 = rowBase + trow * 16 + 2 * r;
        if (row0 < M) {
            *(float4*)&out[row0 * HID + tcol * 4] = make_float4(vlo[0], vlo[1], vlo[2], vlo[3]);
            store_pair_h(outh, row0, tcol * 4, vlo);
#pragma unroll
            for (int c = 0; c < 4; c++) { lsum[c] += vlo[c]; lsq[c] += vlo[c] * vlo[c]; }
        }
        if (row0 + 1 < M) {
            *(float4*)&out[(row0 + 1) * HID + tcol * 4] = make_float4(vhi[0], vhi[1], vhi[2], vhi[3]);
            store_pair_h(outh, row0 + 1, tcol * 4, vhi);
#pragma unroll
            for (int c = 0; c < 4; c++) { lsum[c] += vhi[c]; lsq[c] += vhi[c] * vhi[c]; }
        }
    }
#pragma unroll
    for (int c = 0; c < 4; c++) {
        atomicAdd(&csum[tcol * 4 + c], lsum[c]);
        atomicAdd(&csq[tcol * 4 + c], lsq[c]);
    }
    __syncthreads();
    if (tid < HID) {
        atomicAdd(&statS[tid], csum[tid]);
        atomicAdd(&statQ[tid], csq[tid]);
    }
}

// ---------------- SAGE GEMM: 64-row tiles, occupancy 4, inline BN for self term ----------------
// out = neigh @ W1 + bn_relu(hprev) @ W2 + bias
__global__ __launch_bounds__(256, 4) void gemm_sage_kernel(
    const float* __restrict__ neigh, const float* __restrict__ W1,
    const float* __restrict__ hprev, const float* __restrict__ W2,
    const float* __restrict__ bias, float* __restrict__ out,
    const float* __restrict__ gamma, const float* __restrict__ beta, int layer,
    float* __restrict__ statS, float* __restrict__ statQ, int M, int writeMirror)
{
    __shared__ __align__(16) float Asf[AS64_SIZE];
    __shared__ __align__(16) float Bsf[BS_SIZE];
    __shared__ float csum[HID], csq[HID];

    int tid = threadIdx.x;
    int tcol = tid & 31;
    int trow = tid >> 5;
    int rowBase = blockIdx.x * 64;

    unsigned long long acc[4][4];
#pragma unroll
    for (int r = 0; r < 4; r++)
#pragma unroll
        for (int c = 0; c < 4; c++) acc[r][c] = 0ULL;
    if (tid < HID) { csum[tid] = 0.f; csq[tid] = 0.f; }

    // part 1: neigh @ W1
    for (int kc = 0; kc < HID; kc += 32) {
        __syncthreads();
        stage_A64(Asf, neigh, rowBase, kc, M, tid);
        stage_B(Bsf, W1, kc, tid);
        __syncthreads();
        compute_chunk64(Asf, Bsf, trow, tcol, acc);
    }
    // part 2: bn_relu(hprev) @ W2 (inline BN)
    for (int kc = 0; kc < HID; kc += 32) {
        __syncthreads();
        stage_A64_bn(Asf, hprev, rowBase, kc, M, tid, layer, gamma, beta);
        stage_B(Bsf, W2, kc, tid);
        __syncthreads();
        compute_chunk64(Asf, Bsf, trow, tcol, acc);
    }

    float4 bias4 = __ldg((const float4*)&bias[tcol * 4]);
    float bv[4] = { bias4.x, bias4.y, bias4.z, bias4.w };
    float lsum[4] = {0, 0, 0, 0}, lsq[4] = {0, 0, 0, 0};
#pragma unroll
    for (int r = 0; r < 4; r++) {
        float vlo[4], vhi[4];
#pragma unroll
        for (int c = 0; c < 4; c++) {
            unsigned long long u = acc[r][c];
            vlo[c] = __uint_as_float((unsigned)u) + bv[c];
            vhi[c] = __uint_as_float((unsigned)(u >> 32)) + bv[c];
        }
        int row0 = rowBase + trow * 8 + 2 * r;
        if (row0 < M) {
            *(float4*)&out[row0 * HID + tcol * 4] = make_float4(vlo[0], vlo[1], vlo[2], vlo[3]);
            if (writeMirror) store_pair_h(g_hf, row0, tcol * 4, vlo);
#pragma unroll
            for (int c = 0; c < 4; c++) { lsum[c] += vlo[c]; lsq[c] += vlo[c] * vlo[c]; }
        }
        if (row0 + 1 < M) {
            *(float4*)&out[(row0 + 1) * HID + tcol * 4] = make_float4(vhi[0], vhi[1], vhi[2], vhi[3]);
            if (writeMirror) store_pair_h(g_hf, row0 + 1, tcol * 4, vhi);
#pragma unroll
            for (int c = 0; c < 4; c++) { lsum[c] += vhi[c]; lsq[c] += vhi[c] * vhi[c]; }
        }
    }
#pragma unroll
    for (int c = 0; c < 4; c++) {
        atomicAdd(&csum[tcol * 4 + c], lsum[c]);
        atomicAdd(&csq[tcol * 4 + c], lsq[c]);
    }
    __syncthreads();
    if (tid < HID) {
        atomicAdd(&statS[tid], csum[tid]);
        atomicAdd(&statQ[tid], csq[tid]);
    }
}

// ---------------- fused GIN MLP (128-row tiles, occ 2) ----------------
__global__ __launch_bounds__(256, 2) void gin_mlp_fused_kernel(
    const float* __restrict__ A, const float* __restrict__ W1, const float* __restrict__ b1,
    const float* __restrict__ W2, const float* __restrict__ b2,
    float* __restrict__ out, float* __restrict__ statS, float* __restrict__ statQ, int M)
{
    extern __shared__ __align__(16) float dyn[];
    float* Asf = dyn;
    float* Bsf = dyn + AS_SIZE;
    float* Tsf = dyn + AS_SIZE + BS_SIZE;
    __shared__ float csum[HID], csq[HID];

    int tid = threadIdx.x;
    int tcol = tid & 31;
    int trow = tid >> 5;
    int rowBase = blockIdx.x * 128;

    unsigned long long acc[8][4];
#pragma unroll
    for (int r = 0; r < 8; r++)
#pragma unroll
        for (int c = 0; c < 4; c++) acc[r][c] = 0ULL;
    if (tid < HID) { csum[tid] = 0.f; csq[tid] = 0.f; }

    for (int kc = 0; kc < HID; kc += 32) {
        __syncthreads();
        stage_A(Asf, A, rowBase, kc, M, tid);
        stage_B(Bsf, W1, kc, tid);
        __syncthreads();
        compute_chunk(Asf, Bsf, trow, tcol, acc);
    }

    {
        float4 bias4 = __ldg((const float4*)&b1[tcol * 4]);
        float bv[4] = { bias4.x, bias4.y, bias4.z, bias4.w };
        __syncthreads();
#pragma unroll
        for (int r = 0; r < 8; r++) {
            int row0 = trow * 16 + 2 * r;
#pragma unroll
            for (int c = 0; c < 4; c++) {
                unsigned long long u = acc[r][c];
                float vlo = fmaxf(__uint_as_float((unsigned)u) + bv[c], 0.f);
                float vhi = fmaxf(__uint_as_float((unsigned)(u >> 32)) + bv[c], 0.f);
                int col = tcol * 4 + c;
                Tsf[AS_IDX(col, row0)] = vlo;
                Tsf[AS_IDX(col, row0 + 1)] = vhi;
                acc[r][c] = 0ULL;
            }
        }
    }
    __syncthreads();

    for (int kc = 0; kc < HID; kc += 32) {
        __syncthreads();
        stage_B(Bsf, W2, kc, tid);
        __syncthreads();
        compute_chunk(&Tsf[AS_IDX(kc, 0)], Bsf, trow, tcol, acc);
    }
    gemm_epilogue(acc, b2, out, g_hf, csum, csq, statS, statQ, rowBase, trow, tcol, M, tid);
}

// ---------------- pooling (inline BN finalize for last layer) ----------------
__device__ __forceinline__ int lbound(const int* a, int n, int v) {
    int lo = 0, hi = n;
    while (lo < hi) {
        int mid = (lo + hi) >> 1;
        if (a[mid] < v) lo = mid + 1; else hi = mid;
    }
    return lo;
}

__global__ void pool_kernel(const float* __restrict__ hraw,
                            const int* __restrict__ batch,
                            const float* __restrict__ gamma,
                            const float* __restrict__ beta,
                            float* __restrict__ out) {
    int gg = blockIdx.x;
    int c = threadIdx.x;
    const float invn = 1.0f / (float)N_NODES;
    float m = g_bnsum[2 * HID + c] * invn;
    float var = fmaxf(g_bnsq[2 * HID + c] * invn - m * m, 0.f);
    float sc = __ldg(&gamma[c]) * rsqrtf(var + BN_EPS);
    float sh = __ldg(&beta[c]) - m * sc;

    int start = lbound(batch, N_NODES, gg);
    int end = lbound(batch, N_NODES, gg + 1);
    int cnt = end - start;
    float s = 0.f;
    for (int i = start; i < end; i++) {
        float v = fmaf(hraw[i * HID + c], sc, sh);
        s += fmaxf(v, 0.f);
    }
    out[gg * HID + c] = s / fmaxf((float)cnt, 1.f);
}

// ---------------- launch ----------------
extern "C" void kernel_launch(void* const* d_in, const int* in_sizes, int n_in,
                              void* d_out, int out_size) {
    (void)in_sizes; (void)n_in; (void)out_size;
    const float* x       = (const float*)d_in[0];
    const int*   eidx    = (const int*)d_in[1];
    const int*   batch   = (const int*)d_in[2];
    const float* gin_w1  = (const float*)d_in[3];
    const float* gin_b1  = (const float*)d_in[4];
    const float* gin_w2  = (const float*)d_in[5];
    const float* gin_b2  = (const float*)d_in[6];
    const float* sage_wl = (const float*)d_in[7];
    const float* sage_bl = (const float*)d_in[8];
    const float* sage_wr = (const float*)d_in[9];
    const float* bn_g    = (const float*)d_in[10];
    const float* bn_b    = (const float*)d_in[11];
    float* out = (float*)d_out;

    const int* src = eidx;
    const int* dst = eidx + N_EDGES;

    float *p_h0, *p_h1, *p_ng, *p_t2, *p_bnsum, *p_bnsq;
    cudaGetSymbolAddress((void**)&p_h0, g_h0);
    cudaGetSymbolAddress((void**)&p_h1, g_h1);
    cudaGetSymbolAddress((void**)&p_ng, g_neigh);
    cudaGetSymbolAddress((void**)&p_t2, g_t2);
    cudaGetSymbolAddress((void**)&p_bnsum, g_bnsum);
    cudaGetSymbolAddress((void**)&p_bnsq, g_bnsq);

    const int M = N_NODES;
    const int ginGrid = (M + 127) / 128;             // 391
    const int sageGrid = (M + 63) / 64;              // 782
    const int aggGrid = (N_NODES * 32 + 255) / 256;
    const int edge4Grid = ((N_EDGES + 3) / 4 + 255) / 256;   // 4 edges/thread

    const int fusedSmem = (AS_SIZE + BS_SIZE + TS_SIZE) * 4;  // ~102KB
    static int attr_set = 0;
    if (!attr_set) {
        cudaFuncSetAttribute(gin_mlp_fused_kernel,
                             cudaFuncAttributeMaxDynamicSharedMemorySize, fusedSmem);
        attr_set = 1;
    }

    // CSR build (vectorized hist/scatter, 2-kernel scan)
    zero_init_kernel<<<(N_NODES + 255) / 256, 256>>>();
    hist_kernel<<<edge4Grid, 256>>>(dst);
    scan_part1_kernel<<<SCAN_BLOCKS, 256>>>();
    scan_part2_kernel<<<SCAN_BLOCKS, 256>>>();
    scatter_kernel<<<edge4Grid, 256>>>(src, dst);

    // Layer 0: GIN (fp32 gather; fused MLP; stats -> layer 0; writes f16 mirror)
    gin_agg_kernel<<<aggGrid, 256>>>(x);
    gin_mlp_fused_kernel<<<ginGrid, 256, fusedSmem>>>(p_h0, gin_w1, gin_b1, gin_w2, gin_b2,
                                                      p_h1, p_bnsum + 0 * HID, p_bnsq + 0 * HID, M);

    // SAGE layer 0: agg (neigh only) then GEMM with inline BN self term
    sage_agg_kernel<<<aggGrid, 256>>>(p_ng, bn_g + 0 * HID, bn_b + 0 * HID, 0);
    gemm_sage_kernel<<<sageGrid, 256>>>(p_ng, sage_wl, p_h1, sage_wr, sage_bl, p_h0,
                                        bn_g + 0 * HID, bn_b + 0 * HID, 0,
                                        p_bnsum + 1 * HID, p_bnsq + 1 * HID, M, 1);

    // SAGE layer 1
    sage_agg_kernel<<<aggGrid, 256>>>(p_ng, bn_g + 1 * HID, bn_b + 1 * HID, 1);
    gemm_sage_kernel<<<sageGrid, 256>>>(p_ng, sage_wl + HID * HID, p_h0, sage_wr + HID * HID,
                                        sage_bl + HID, p_t2,
                                        bn_g + 1 * HID, bn_b + 1 * HID, 1,
                                        p_bnsum + 2 * HID, p_bnsq + 2 * HID, M, 0);

    // global mean pool (inline BN finalize for layer 2)
    pool_kernel<<<N_GRAPHS, HID>>>(p_t2, batch, bn_g + 2 * HID, bn_b + 2 * HID, out);
}

// round 17
// speedup vs baseline: 1.0176x; 1.0176x over previous
#include <cuda_runtime.h>
#include <cuda_fp16.h>
#include <cstdint>

#define N_NODES 50000
#define N_EDGES 600000
#define HID     128
#define N_GRAPHS 512
#define BN_EPS  1e-5f
#define SCAN_BLOCKS ((N_NODES + 255) / 256)   // 196

#define GRID_SYNC()    asm volatile("griddepcontrol.wait;" ::: "memory")
#define GRID_TRIGGER() asm volatile("griddepcontrol.launch_dependents;" ::: "memory")

// ---------------- scratch ----------------
__device__ float g_h0[N_NODES * HID];
__device__ float g_h1[N_NODES * HID];
__device__ float g_neigh[N_NODES * HID];
__device__ float g_t2[N_NODES * HID];
__device__ __half g_hf[N_NODES * HID];   // fp16 mirror of layer outputs (gather source)

__device__ int   g_deg[N_NODES];
__device__ int   g_off[N_NODES + 1];
__device__ int   g_cur[N_NODES];
__device__ int   g_csr[N_EDGES];
__device__ float g_invdeg[N_NODES];
__device__ int   g_blk[SCAN_BLOCKS];

__device__ float g_bnsum[3 * HID];
__device__ float g_bnsq[3 * HID];

// ---------------- helpers ----------------
__device__ __forceinline__ unsigned long long pack_dup(float x) {
    unsigned long long d;
    asm("mov.b64 %0,{%1,%1};" : "=l"(d) : "f"(x));
    return d;
}

// 128-row transposed A layout (GIN): (k,row) at k*132 + 4*(k>>2) + row
#define AS_IDX(k, row) ((k) * 132 + 4 * ((k) >> 2) + (row))
#define AS_SIZE 4256
// 64-row transposed A layout (SAGE)
#define AS64_IDX(k, row) ((k) * 68 + 4 * ((k) >> 2) + (row))
#define AS64_SIZE 2208
// B layout: (k,n) at k*132 + n
#define BS_IDX(k, n) ((k) * 132 + (n))
#define BS_SIZE 4224
#define TS_SIZE 17024

// ---------------- setup kernels ----------------
__global__ void zero_init_kernel() {
    int i = blockIdx.x * blockDim.x + threadIdx.x;
    if (i < N_NODES) g_deg[i] = 0;
    if (i < 3 * HID) { g_bnsum[i] = 0.f; g_bnsq[i] = 0.f; }
}

__global__ void hist_kernel(const int* __restrict__ dst) {
    int e = blockIdx.x * blockDim.x + threadIdx.x;
    int d = (e < N_EDGES) ? __ldg(&dst[e]) : 0;   // input: safe pre-sync
    GRID_SYNC();
    if (e < N_EDGES) atomicAdd(&g_deg[d], 1);
}

__global__ void scan_part1_kernel() {
    GRID_SYNC();
    __shared__ int sh[256];
    int t = threadIdx.x;
    int i = blockIdx.x * 256 + t;
    sh[t] = (i < N_NODES) ? g_deg[i] : 0;
    __syncthreads();
    for (int off = 128; off > 0; off >>= 1) {
        if (t < off) sh[t] += sh[t + off];
        __syncthreads();
    }
    if (t == 0) g_blk[blockIdx.x] = sh[0];
}

// fused: every block scans block sums in smem, then its local scan
__global__ void scan_part2_kernel() {
    GRID_SYNC();
    __shared__ int bs[256];
    __shared__ int sh[256];
    int t = threadIdx.x;
    bs[t] = (t < SCAN_BLOCKS) ? g_blk[t] : 0;
    __syncthreads();
    for (int off = 1; off < 256; off <<= 1) {
        int u = (t >= off) ? bs[t - off] : 0;
        __syncthreads();
        bs[t] += u;
        __syncthreads();
    }
    if (blockIdx.x == 0 && t == 0) g_off[N_NODES] = bs[SCAN_BLOCKS - 1];
    int base = bs[blockIdx.x] - ((blockIdx.x < SCAN_BLOCKS) ? g_blk[blockIdx.x] : 0);

    int i = blockIdx.x * 256 + t;
    int d = (i < N_NODES) ? g_deg[i] : 0;
    sh[t] = d;
    __syncthreads();
    for (int off = 1; off < 256; off <<= 1) {
        int u = (t >= off) ? sh[t - off] : 0;
        __syncthreads();
        sh[t] += u;
        __syncthreads();
    }
    if (i < N_NODES) {
        int run = base + sh[t] - d;
        g_off[i] = run;
        g_cur[i] = run;
        g_invdeg[i] = 1.0f / (float)max(d, 1);
    }
}

__global__ void scatter_kernel(const int* __restrict__ src, const int* __restrict__ dst) {
    int e = blockIdx.x * blockDim.x + threadIdx.x;
    int d = 0, s = 0;
    if (e < N_EDGES) { d = __ldg(&dst[e]); s = __ldg(&src[e]); }  // inputs: safe pre-sync
    GRID_SYNC();
    if (e < N_EDGES) {
        int p = atomicAdd(&g_cur[d], 1);
        g_csr[p] = s;
    }
    GRID_TRIGGER();
}

// ---------------- GIN aggregation (warp per node, fp32 gather) ----------------
__global__ void gin_agg_kernel(const float* __restrict__ x) {
    int w = (blockIdx.x * blockDim.x + threadIdx.x) >> 5;
    int lane = threadIdx.x & 31;
    const float4* x4 = (const float4*)x;
    float4 acc = make_float4(0.f, 0.f, 0.f, 0.f);
    if (w < N_NODES) acc = __ldg(&x4[w * 32 + lane]);   // input: safe pre-sync
    GRID_SYNC();
    if (w >= N_NODES) return;
    int e = g_off[w], end = g_off[w + 1];
    for (; e + 4 <= end; e += 4) {
        int s0 = g_csr[e + 0], s1 = g_csr[e + 1], s2 = g_csr[e + 2], s3 = g_csr[e + 3];
        float4 v0 = __ldg(&x4[s0 * 32 + lane]);
        float4 v1 = __ldg(&x4[s1 * 32 + lane]);
        float4 v2 = __ldg(&x4[s2 * 32 + lane]);
        float4 v3 = __ldg(&x4[s3 * 32 + lane]);
        acc.x += v0.x + v1.x + v2.x + v3.x;
        acc.y += v0.y + v1.y + v2.y + v3.y;
        acc.z += v0.z + v1.z + v2.z + v3.z;
        acc.w += v0.w + v1.w + v2.w + v3.w;
    }
    for (; e < end; e++) {
        int s0 = g_csr[e];
        float4 v0 = __ldg(&x4[s0 * 32 + lane]);
        acc.x += v0.x; acc.y += v0.y; acc.z += v0.z; acc.w += v0.w;
    }
    GRID_TRIGGER();
    ((float4*)g_h0)[w * 32 + lane] = acc;
}

__device__ __forceinline__ float4 bn_relu4(float4 h, float4 sc, float4 sh) {
    float4 r;
    r.x = fmaxf(fmaf(h.x, sc.x, sh.x), 0.f);
    r.y = fmaxf(fmaf(h.y, sc.y, sh.y), 0.f);
    r.z = fmaxf(fmaf(h.z, sc.z, sh.z), 0.f);
    r.w = fmaxf(fmaf(h.w, sc.w, sh.w), 0.f);
    return r;
}

__device__ __forceinline__ void bn_coeffs(int layer, int c0,
                                          const float* __restrict__ gamma,
                                          const float* __restrict__ beta,
                                          float4& sc, float4& sh) {
    const float invn = 1.0f / (float)N_NODES;
    float4 s1 = *(const float4*)&g_bnsum[layer * HID + c0];
    float4 s2 = *(const float4*)&g_bnsq[layer * HID + c0];
    float4 gm = __ldg((const float4*)&gamma[c0]);
    float4 bt = __ldg((const float4*)&beta[c0]);
    float m, var;
    m = s1.x * invn; var = fmaxf(s2.x * invn - m * m, 0.f);
    sc.x = gm.x * rsqrtf(var + BN_EPS); sh.x = bt.x - m * sc.x;
    m = s1.y * invn; var = fmaxf(s2.y * invn - m * m, 0.f);
    sc.y = gm.y * rsqrtf(var + BN_EPS); sh.y = bt.y - m * sc.y;
    m = s1.z * invn; var = fmaxf(s2.z * invn - m * m, 0.f);
    sc.z = gm.z * rsqrtf(var + BN_EPS); sh.z = bt.z - m * sc.z;
    m = s1.w * invn; var = fmaxf(s2.w * invn - m * m, 0.f);
    sc.w = gm.w * rsqrtf(var + BN_EPS); sh.w = bt.w - m * sc.w;
}

// SAGE aggregation: neighbors from fp16 mirror only
__global__ void sage_agg_kernel(float* __restrict__ neigh,
                                const float* __restrict__ gamma,
                                const float* __restrict__ beta,
                                int layer) {
    int w = (blockIdx.x * blockDim.x + threadIdx.x) >> 5;
    int lane = threadIdx.x & 31;
    int e = 0, end = 0;
    float id = 1.f;
    if (w < N_NODES) {   // CSR written >=2 kernels back: safe pre-sync
        e = g_off[w]; end = g_off[w + 1]; id = g_invdeg[w];
    }
    GRID_SYNC();
    if (w >= N_NODES) return;
    float4 sc, sh;
    bn_coeffs(layer, lane * 4, gamma, beta, sc, sh);

    const uint2* hh = (const uint2*)g_hf;
    float4 acc = make_float4(0.f, 0.f, 0.f, 0.f);
#define GATH_H(sx, vr) { \
        uint2 u = __ldg(&hh[(sx) * 32 + lane]); \
        float2 f0 = __half22float2(*(__half2*)&u.x); \
        float2 f1 = __half22float2(*(__half2*)&u.y); \
        vr = bn_relu4(make_float4(f0.x, f0.y, f1.x, f1.y), sc, sh); }
    for (; e + 4 <= end; e += 4) {
        int s0 = g_csr[e + 0], s1 = g_csr[e + 1], s2 = g_csr[e + 2], s3 = g_csr[e + 3];
        float4 v0, v1, v2, v3;
        GATH_H(s0, v0); GATH_H(s1, v1); GATH_H(s2, v2); GATH_H(s3, v3);
        acc.x += v0.x + v1.x + v2.x + v3.x;
        acc.y += v0.y + v1.y + v2.y + v3.y;
        acc.z += v0.z + v1.z + v2.z + v3.z;
        acc.w += v0.w + v1.w + v2.w + v3.w;
    }
    for (; e < end; e++) {
        int s0 = g_csr[e];
        float4 v0;
        GATH_H(s0, v0);
        acc.x += v0.x; acc.y += v0.y; acc.z += v0.z; acc.w += v0.w;
    }
#undef GATH_H
    GRID_TRIGGER();
    acc.x *= id; acc.y *= id; acc.z *= id; acc.w *= id;
    ((float4*)neigh)[w * 32 + lane] = acc;
}

// ---------------- GEMM building blocks ----------------
__device__ __forceinline__ void stage_A(float* Asf, const float* __restrict__ A,
                                        int rowBase, int kc, int M, int tid) {
#pragma unroll
    for (int i = 0; i < 4; i++) {
        int f = tid + 256 * i;
        int row = f >> 3, kq = f & 7;
        int grow = rowBase + row; if (grow >= M) grow = M - 1;
        float4 v = __ldg((const float4*)&A[grow * HID + kc + kq * 4]);
        int k0 = kq * 4;
        Asf[AS_IDX(k0 + 0, row)] = v.x;
        Asf[AS_IDX(k0 + 1, row)] = v.y;
        Asf[AS_IDX(k0 + 2, row)] = v.z;
        Asf[AS_IDX(k0 + 3, row)] = v.w;
    }
}

__device__ __forceinline__ void stage_A64(float* Asf, const float* __restrict__ A,
                                          int rowBase, int kc, int M, int tid) {
#pragma unroll
    for (int i = 0; i < 2; i++) {
        int f = tid + 256 * i;
        int row = f >> 3, kq = f & 7;
        int grow = rowBase + row; if (grow >= M) grow = M - 1;
        float4 v = __ldg((const float4*)&A[grow * HID + kc + kq * 4]);
        int k0 = kq * 4;
        Asf[AS64_IDX(k0 + 0, row)] = v.x;
        Asf[AS64_IDX(k0 + 1, row)] = v.y;
        Asf[AS64_IDX(k0 + 2, row)] = v.z;
        Asf[AS64_IDX(k0 + 3, row)] = v.w;
    }
}

// stage bn_relu(hprev) 64-row chunk: coeffs computed inline
__device__ __forceinline__ void stage_A64_bn(float* Asf, const float* __restrict__ A,
                                             int rowBase, int kc, int M, int tid,
                                             int layer,
                                             const float* __restrict__ gamma,
                                             const float* __restrict__ beta) {
#pragma unroll
    for (int i = 0; i < 2; i++) {
        int f = tid + 256 * i;
        int row = f >> 3, kq = f & 7;
        int grow = rowBase + row; if (grow >= M) grow = M - 1;
        int c0 = kc + kq * 4;
        float4 sc, sh;
        bn_coeffs(layer, c0, gamma, beta, sc, sh);
        float4 v = bn_relu4(__ldg((const float4*)&A[grow * HID + c0]), sc, sh);
        int k0 = kq * 4;
        Asf[AS64_IDX(k0 + 0, row)] = v.x;
        Asf[AS64_IDX(k0 + 1, row)] = v.y;
        Asf[AS64_IDX(k0 + 2, row)] = v.z;
        Asf[AS64_IDX(k0 + 3, row)] = v.w;
    }
}

__device__ __forceinline__ void stage_B(float* Bsf, const float* __restrict__ W,
                                        int kc, int tid) {
#pragma unroll
    for (int i = 0; i < 4; i++) {
        int f = tid + 256 * i;
        int k = f >> 5, n4 = f & 31;
        float4 v = __ldg((const float4*)&W[(kc + k) * HID + n4 * 4]);
        *(float4*)&Bsf[BS_IDX(k, n4 * 4)] = v;
    }
}

__device__ __forceinline__ void compute_chunk(const float* __restrict__ Afrag,
                                              const float* __restrict__ Bsf,
                                              int trow, int tcol,
                                              unsigned long long acc[8][4]) {
#pragma unroll 8
    for (int k = 0; k < 32; k++) {
        const float* ar = &Afrag[k * 132 + 4 * (k >> 2) + trow * 16];
        unsigned long long a[8];
        ulonglong2 t;
        t = *(const ulonglong2*)(ar + 0);  a[0] = t.x; a[1] = t.y;
        t = *(const ulonglong2*)(ar + 4);  a[2] = t.x; a[3] = t.y;
        t = *(const ulonglong2*)(ar + 8);  a[4] = t.x; a[5] = t.y;
        t = *(const ulonglong2*)(ar + 12); a[6] = t.x; a[7] = t.y;
        float4 b4 = *(const float4*)&Bsf[BS_IDX(k, tcol * 4)];
        unsigned long long bb0 = pack_dup(b4.x);
        unsigned long long bb1 = pack_dup(b4.y);
        unsigned long long bb2 = pack_dup(b4.z);
        unsigned long long bb3 = pack_dup(b4.w);
#pragma unroll
        for (int r = 0; r < 8; r++) {
            asm("fma.rn.f32x2 %0,%1,%2,%0;" : "+l"(acc[r][0]) : "l"(a[r]), "l"(bb0));
            asm("fma.rn.f32x2 %0,%1,%2,%0;" : "+l"(acc[r][1]) : "l"(a[r]), "l"(bb1));
            asm("fma.rn.f32x2 %0,%1,%2,%0;" : "+l"(acc[r][2]) : "l"(a[r]), "l"(bb2));
            asm("fma.rn.f32x2 %0,%1,%2,%0;" : "+l"(acc[r][3]) : "l"(a[r]), "l"(bb3));
        }
    }
}

__device__ __forceinline__ void compute_chunk64(const float* __restrict__ Afrag,
                                                const float* __restrict__ Bsf,
                                                int trow, int tcol,
                                                unsigned long long acc[4][4]) {
#pragma unroll 8
    for (int k = 0; k < 32; k++) {
        const float* ar = &Afrag[k * 68 + 4 * (k >> 2) + trow * 8];
        unsigned long long a[4];
        ulonglong2 t;
        t = *(const ulonglong2*)(ar + 0); a[0] = t.x; a[1] = t.y;
        t = *(const ulonglong2*)(ar + 4); a[2] = t.x; a[3] = t.y;
        float4 b4 = *(const float4*)&Bsf[BS_IDX(k, tcol * 4)];
        unsigned long long bb0 = pack_dup(b4.x);
        unsigned long long bb1 = pack_dup(b4.y);
        unsigned long long bb2 = pack_dup(b4.z);
        unsigned long long bb3 = pack_dup(b4.w);
#pragma unroll
        for (int r = 0; r < 4; r++) {
            asm("fma.rn.f32x2 %0,%1,%2,%0;" : "+l"(acc[r][0]) : "l"(a[r]), "l"(bb0));
            asm("fma.rn.f32x2 %0,%1,%2,%0;" : "+l"(acc[r][1]) : "l"(a[r]), "l"(bb1));
            asm("fma.rn.f32x2 %0,%1,%2,%0;" : "+l"(acc[r][2]) : "l"(a[r]), "l"(bb2));
            asm("fma.rn.f32x2 %0,%1,%2,%0;" : "+l"(acc[r][3]) : "l"(a[r]), "l"(bb3));
        }
    }
}

__device__ __forceinline__ void store_pair_h(__half* __restrict__ outh, int row, int c0,
                                             const float* v) {
    __half2 a = __float22half2_rn(make_float2(v[0], v[1]));
    __half2 b = __float22half2_rn(make_float2(v[2], v[3]));
    uint2 u;
    u.x = *(uint32_t*)&a; u.y = *(uint32_t*)&b;
    *(uint2*)&outh[row * HID + c0] = u;
}

// 128-row epilogue (GIN): bias + store f32 + f16 mirror + BN stats
__device__ __forceinline__ void gemm_epilogue(unsigned long long acc[8][4],
                                              const float* __restrict__ bias,
                                              float* __restrict__ out,
                                              __half* __restrict__ outh,
                                              float* csum, float* csq,
                                              float* statS, float* statQ,
                                              int rowBase, int trow, int tcol,
                                              int M, int tid) {
    float4 bias4 = __ldg((const float4*)&bias[tcol * 4]);
    float bv[4] = { bias4.x, bias4.y, bias4.z, bias4.w };
    float lsum[4] = {0, 0, 0, 0}, lsq[4] = {0, 0, 0, 0};
#pragma unroll
    for (int r = 0; r < 8; r++) {
        float vlo[4], vhi[4];
#pragma unroll
        for (int c = 0; c < 4; c++) {
            unsigned long long u = acc[r][c];
            vlo[c] = __uint_as_float((unsigned)u) + bv[c];
            vhi[c] = __uint_as_float((unsigned)(u >> 32)) + bv[c];
        }
        int row0 = rowBase + trow * 16 + 2 * r;
        if (row0 < M) {
            *(float4*)&out[row0 * HID + tcol * 4] = make_float4(vlo[0], vlo[1], vlo[2], vlo[3]);
            store_pair_h(outh, row0, tcol * 4, vlo);
#pragma unroll
            for (int c = 0; c < 4; c++) { lsum[c] += vlo[c]; lsq[c] += vlo[c] * vlo[c]; }
        }
        if (row0 + 1 < M) {
            *(float4*)&out[(row0 + 1) * HID + tcol * 4] = make_float4(vhi[0], vhi[1], vhi[2], vhi[3]);
            store_pair_h(outh, row0 + 1, tcol * 4, vhi);
#pragma unroll
            for (int c = 0; c < 4; c++) { lsum[c] += vhi[c]; lsq[c] += vhi[c] * vhi[c]; }
        }
    }
#pragma unroll
    for (int c = 0; c < 4; c++) {
        atomicAdd(&csum[tcol * 4 + c], lsum[c]);
        atomicAdd(&csq[tcol * 4 + c], lsq[c]);
    }
    __syncthreads();
    if (tid < HID) {
        atomicAdd(&statS[tid], csum[tid]);
        atomicAdd(&statQ[tid], csq[tid]);
    }
}

// ---------------- SAGE GEMM: 64-row tiles, occupancy 4, inline BN self term ----------------
__global__ __launch_bounds__(256, 4) void gemm_sage_kernel(
    const float* __restrict__ neigh, const float* __restrict__ W1,
    const float* __restrict__ hprev, const float* __restrict__ W2,
    const float* __restrict__ bias, float* __restrict__ out,
    const float* __restrict__ gamma, const float* __restrict__ beta, int layer,
    float* __restrict__ statS, float* __restrict__ statQ, int M, int writeMirror)
{
    __shared__ __align__(16) float Asf[AS64_SIZE];
    __shared__ __align__(16) float Bsf[BS_SIZE];
    __shared__ float csum[HID], csq[HID];

    int tid = threadIdx.x;
    int tcol = tid & 31;
    int trow = tid >> 5;
    int rowBase = blockIdx.x * 64;

    unsigned long long acc[4][4];
#pragma unroll
    for (int r = 0; r < 4; r++)
#pragma unroll
        for (int c = 0; c < 4; c++) acc[r][c] = 0ULL;
    if (tid < HID) { csum[tid] = 0.f; csq[tid] = 0.f; }

    // pre-sync: stage W1 chunk 0 (weights are kernel inputs)
    stage_B(Bsf, W1, 0, tid);
    GRID_SYNC();

    // part 1: neigh @ W1
    for (int kc = 0; kc < HID; kc += 32) {
        if (kc) { __syncthreads(); stage_B(Bsf, W1, kc, tid); }
        stage_A64(Asf, neigh, rowBase, kc, M, tid);
        __syncthreads();
        compute_chunk64(Asf, Bsf, trow, tcol, acc);
    }
    // part 2: bn_relu(hprev) @ W2 (inline BN)
    for (int kc = 0; kc < HID; kc += 32) {
        __syncthreads();
        stage_A64_bn(Asf, hprev, rowBase, kc, M, tid, layer, gamma, beta);
        stage_B(Bsf, W2, kc, tid);
        __syncthreads();
        compute_chunk64(Asf, Bsf, trow, tcol, acc);
    }
    GRID_TRIGGER();

    float4 bias4 = __ldg((const float4*)&bias[tcol * 4]);
    float bv[4] = { bias4.x, bias4.y, bias4.z, bias4.w };
    float lsum[4] = {0, 0, 0, 0}, lsq[4] = {0, 0, 0, 0};
#pragma unroll
    for (int r = 0; r < 4; r++) {
        float vlo[4], vhi[4];
#pragma unroll
        for (int c = 0; c < 4; c++) {
            unsigned long long u = acc[r][c];
            vlo[c] = __uint_as_float((unsigned)u) + bv[c];
            vhi[c] = __uint_as_float((unsigned)(u >> 32)) + bv[c];
        }
        int row0 = rowBase + trow * 8 + 2 * r;
        if (row0 < M) {
            *(float4*)&out[row0 * HID + tcol * 4] = make_float4(vlo[0], vlo[1], vlo[2], vlo[3]);
            if (writeMirror) store_pair_h(g_hf, row0, tcol * 4, vlo);
#pragma unroll
            for (int c = 0; c < 4; c++) { lsum[c] += vlo[c]; lsq[c] += vlo[c] * vlo[c]; }
        }
        if (row0 + 1 < M) {
            *(float4*)&out[(row0 + 1) * HID + tcol * 4] = make_float4(vhi[0], vhi[1], vhi[2], vhi[3]);
            if (writeMirror) store_pair_h(g_hf, row0 + 1, tcol * 4, vhi);
#pragma unroll
            for (int c = 0; c < 4; c++) { lsum[c] += vhi[c]; lsq[c] += vhi[c] * vhi[c]; }
        }
    }
#pragma unroll
    for (int c = 0; c < 4; c++) {
        atomicAdd(&csum[tcol * 4 + c], lsum[c]);
        atomicAdd(&csq[tcol * 4 + c], lsq[c]);
    }
    __syncthreads();
    if (tid < HID) {
        atomicAdd(&statS[tid], csum[tid]);
        atomicAdd(&statQ[tid], csq[tid]);
    }
}

// ---------------- fused GIN MLP (128-row tiles, occ 2) ----------------
__global__ __launch_bounds__(256, 2) void gin_mlp_fused_kernel(
    const float* __restrict__ A, const float* __restrict__ W1, const float* __restrict__ b1,
    const float* __restrict__ W2, const float* __restrict__ b2,
    float* __restrict__ out, float* __restrict__ statS, float* __restrict__ statQ, int M)
{
    extern __shared__ __align__(16) float dyn[];
    float* Asf = dyn;
    float* Bsf = dyn + AS_SIZE;
    float* Tsf = dyn + AS_SIZE + BS_SIZE;
    __shared__ float csum[HID], csq[HID];

    int tid = threadIdx.x;
    int tcol = tid & 31;
    int trow = tid >> 5;
    int rowBase = blockIdx.x * 128;

    unsigned long long acc[8][4];
#pragma unroll
    for (int r = 0; r < 8; r++)
#pragma unroll
        for (int c = 0; c < 4; c++) acc[r][c] = 0ULL;
    if (tid < HID) { csum[tid] = 0.f; csq[tid] = 0.f; }

    // pre-sync: stage W1 chunk 0 (weights are kernel inputs)
    stage_B(Bsf, W1, 0, tid);
    GRID_SYNC();

    for (int kc = 0; kc < HID; kc += 32) {
        if (kc) { __syncthreads(); stage_B(Bsf, W1, kc, tid); }
        stage_A(Asf, A, rowBase, kc, M, tid);
        __syncthreads();
        compute_chunk(Asf, Bsf, trow, tcol, acc);
    }

    {
        float4 bias4 = __ldg((const float4*)&b1[tcol * 4]);
        float bv[4] = { bias4.x, bias4.y, bias4.z, bias4.w };
        __syncthreads();
#pragma unroll
        for (int r = 0; r < 8; r++) {
            int row0 = trow * 16 + 2 * r;
#pragma unroll
            for (int c = 0; c < 4; c++) {
                unsigned long long u = acc[r][c];
                float vlo = fmaxf(__uint_as_float((unsigned)u) + bv[c], 0.f);
                float vhi = fmaxf(__uint_as_float((unsigned)(u >> 32)) + bv[c], 0.f);
                int col = tcol * 4 + c;
                Tsf[AS_IDX(col, row0)] = vlo;
                Tsf[AS_IDX(col, row0 + 1)] = vhi;
                acc[r][c] = 0ULL;
            }
        }
    }
    __syncthreads();

    for (int kc = 0; kc < HID; kc += 32) {
        __syncthreads();
        stage_B(Bsf, W2, kc, tid);
        __syncthreads();
        compute_chunk(&Tsf[AS_IDX(kc, 0)], Bsf, trow, tcol, acc);
    }
    GRID_TRIGGER();
    gemm_epilogue(acc, b2, out, g_hf, csum, csq, statS, statQ, rowBase, trow, tcol, M, tid);
}

// ---------------- pooling (inline BN finalize for last layer) ----------------
__device__ __forceinline__ int lbound(const int* a, int n, int v) {
    int lo = 0, hi = n;
    while (lo < hi) {
        int mid = (lo + hi) >> 1;
        if (a[mid] < v) lo = mid + 1; else hi = mid;
    }
    return lo;
}

__global__ void pool_kernel(const float* __restrict__ hraw,
                            const int* __restrict__ batch,
                            const float* __restrict__ gamma,
                            const float* __restrict__ beta,
                            float* __restrict__ out) {
    int gg = blockIdx.x;
    int c = threadIdx.x;
    // pre-sync: binary search on input batch array
    int start = lbound(batch, N_NODES, gg);
    int end = lbound(batch, N_NODES, gg + 1);
    GRID_SYNC();
    const float invn = 1.0f / (float)N_NODES;
    float m = g_bnsum[2 * HID + c] * invn;
    float var = fmaxf(g_bnsq[2 * HID + c] * invn - m * m, 0.f);
    float sc = __ldg(&gamma[c]) * rsqrtf(var + BN_EPS);
    float sh = __ldg(&beta[c]) - m * sc;

    int cnt = end - start;
    float s = 0.f;
    for (int i = start; i < end; i++) {
        float v = fmaf(hraw[i * HID + c], sc, sh);
        s += fmaxf(v, 0.f);
    }
    out[gg * HID + c] = s / fmaxf((float)cnt, 1.f);
}

// ---------------- launch helper (PDL) ----------------
static void launchx(const void* fn, int grid, int block, size_t smem,
                    void** args, int pdl) {
    cudaLaunchConfig_t cfg = {};
    cfg.gridDim = dim3((unsigned)grid, 1, 1);
    cfg.blockDim = dim3((unsigned)block, 1, 1);
    cfg.dynamicSmemBytes = smem;
    cfg.stream = 0;
    cudaLaunchAttribute at;
    if (pdl) {
        at.id = cudaLaunchAttributeProgrammaticStreamSerialization;
        at.val.programmaticStreamSerializationAllowed = 1;
        cfg.attrs = &at;
        cfg.numAttrs = 1;
    }
    cudaLaunchKernelExC(&cfg, fn, args);
}

// ---------------- launch ----------------
extern "C" void kernel_launch(void* const* d_in, const int* in_sizes, int n_in,
                              void* d_out, int out_size) {
    (void)in_sizes; (void)n_in; (void)out_size;
    const float* x       = (const float*)d_in[0];
    const int*   eidx    = (const int*)d_in[1];
    const int*   batch   = (const int*)d_in[2];
    const float* gin_w1  = (const float*)d_in[3];
    const float* gin_b1  = (const float*)d_in[4];
    const float* gin_w2  = (const float*)d_in[5];
    const float* gin_b2  = (const float*)d_in[6];
    const float* sage_wl = (const float*)d_in[7];
    const float* sage_bl = (const float*)d_in[8];
    const float* sage_wr = (const float*)d_in[9];
    const float* bn_g    = (const float*)d_in[10];
    const float* bn_b    = (const float*)d_in[11];
    float* out = (float*)d_out;

    const int* src = eidx;
    const int* dst = eidx + N_EDGES;

    float *p_h0, *p_h1, *p_ng, *p_t2, *p_bnsum, *p_bnsq;
    cudaGetSymbolAddress((void**)&p_h0, g_h0);
    cudaGetSymbolAddress((void**)&p_h1, g_h1);
    cudaGetSymbolAddress((void**)&p_ng, g_neigh);
    cudaGetSymbolAddress((void**)&p_t2, g_t2);
    cudaGetSymbolAddress((void**)&p_bnsum, g_bnsum);
    cudaGetSymbolAddress((void**)&p_bnsq, g_bnsq);

    const int M = N_NODES;
    const int ginGrid = (M + 127) / 128;             // 391
    const int sageGrid = (M + 63) / 64;              // 782
    const int aggGrid = (N_NODES * 32 + 255) / 256;
    const int edgeGrid = (N_EDGES + 255) / 256;

    const int fusedSmem = (AS_SIZE + BS_SIZE + TS_SIZE) * 4;  // ~102KB
    static int attr_set = 0;
    if (!attr_set) {
        cudaFuncSetAttribute(gin_mlp_fused_kernel,
                             cudaFuncAttributeMaxDynamicSharedMemorySize, fusedSmem);
        attr_set = 1;
    }

    // pointer locals for arg packing
    const float* gm0 = bn_g + 0 * HID; const float* bt0 = bn_b + 0 * HID;
    const float* gm1 = bn_g + 1 * HID; const float* bt1 = bn_b + 1 * HID;
    const float* gm2 = bn_g + 2 * HID; const float* bt2 = bn_b + 2 * HID;
    float* st0 = p_bnsum + 0 * HID; float* sq0 = p_bnsq + 0 * HID;
    float* st1 = p_bnsum + 1 * HID; float* sq1 = p_bnsq + 1 * HID;
    float* st2 = p_bnsum + 2 * HID; float* sq2 = p_bnsq + 2 * HID;
    const float* wl0 = sage_wl; const float* wr0 = sage_wr;
    const float* wl1 = sage_wl + HID * HID; const float* wr1 = sage_wr + HID * HID;
    const float* bl0 = sage_bl; const float* bl1 = sage_bl + HID;
    int l0 = 0, l1 = 1, mM = M, mir1 = 1, mir0 = 0;

    // CSR build
    zero_init_kernel<<<(N_NODES + 255) / 256, 256>>>();
    { void* a[] = { (void*)&dst };
      launchx((const void*)hist_kernel, edgeGrid, 256, 0, a, 1); }
    launchx((const void*)scan_part1_kernel, SCAN_BLOCKS, 256, 0, nullptr, 1);
    launchx((const void*)scan_part2_kernel, SCAN_BLOCKS, 256, 0, nullptr, 1);
    { void* a[] = { (void*)&src, (void*)&dst };
      launchx((const void*)scatter_kernel, edgeGrid, 256, 0, a, 1); }

    // Layer 0: GIN
    { void* a[] = { (void*)&x };
      launchx((const void*)gin_agg_kernel, aggGrid, 256, 0, a, 1); }
    { void* a[] = { (void*)&p_h0, (void*)&gin_w1, (void*)&gin_b1, (void*)&gin_w2,
                    (void*)&gin_b2, (void*)&p_h1, (void*)&st0, (void*)&sq0, (void*)&mM };
      launchx((const void*)gin_mlp_fused_kernel, ginGrid, 256, fusedSmem, a, 1); }

    // SAGE layer 0
    { void* a[] = { (void*)&p_ng, (void*)&gm0, (void*)&bt0, (void*)&l0 };
      launchx((const void*)sage_agg_kernel, aggGrid, 256, 0, a, 1); }
    { void* a[] = { (void*)&p_ng, (void*)&wl0, (void*)&p_h1, (void*)&wr0, (void*)&bl0,
                    (void*)&p_h0, (void*)&gm0, (void*)&bt0, (void*)&l0,
                    (void*)&st1, (void*)&sq1, (void*)&mM, (void*)&mir1 };
      launchx((const void*)gemm_sage_kernel, sageGrid, 256, 0, a, 1); }

    // SAGE layer 1
    { void* a[] = { (void*)&p_ng, (void*)&gm1, (void*)&bt1, (void*)&l1 };
      launchx((const void*)sage_agg_kernel, aggGrid, 256, 0, a, 1); }
    { void* a[] = { (void*)&p_ng, (void*)&wl1, (void*)&p_h0, (void*)&wr1, (void*)&bl1,
                    (void*)&p_t2, (void*)&gm1, (void*)&bt1, (void*)&l1,
                    (void*)&st2, (void*)&sq2, (void*)&mM, (void*)&mir0 };
      launchx((const void*)gemm_sage_kernel, sageGrid, 256, 0, a, 1); }

    // global mean pool
    { void* a[] = { (void*)&p_t2, (void*)&batch, (void*)&gm2, (void*)&bt2, (void*)&out };
      launchx((const void*)pool_kernel, N_GRAPHS, HID, 0, a, 1); }
}